// round 2
// baseline (speedup 1.0000x reference)
#include <cuda_runtime.h>
#include <cfloat>
#include <math.h>

// Problem constants (shapes are fixed by the dataset)
#define NN   20000      // nodes
#define NE   320000     // edges (before self-loops)
#define HC   512        // HEADS*OUT_CH
#define NH   4          // heads
#define OC   128        // out channels per head

// -------- scratch (static device globals; no runtime allocation) --------
__device__ float g_xl[(size_t)NN * HC];   // projected features [N, 512]
__device__ float g_as[NN * NH];           // per-node src attention half
__device__ float g_ad[NN * NH];           // per-node dst attention half
__device__ float g_amax[NN * NH];         // segment max per (dst, head)
__device__ float g_den[NN * NH];          // segment sum per (dst, head)

// ---------------- init: zero output accumulator, reset segment state ----
__global__ void k_init(float* __restrict__ out) {
    int i = blockIdx.x * blockDim.x + threadIdx.x;
    if (i < NN * OC) out[i] = 0.f;
    if (i < NN * NH) { g_amax[i] = -FLT_MAX; g_den[i] = 0.f; }
}

// ---------------- GEMM: g_xl = x @ W   (M=20000, K=N=512, fp32) ---------
__global__ __launch_bounds__(256) void k_gemm(const float* __restrict__ A,
                                              const float* __restrict__ B) {
    const int K = 512, N = 512;
    __shared__ float As[8][128];
    __shared__ float Bs[8][128];

    const int tid  = threadIdx.x;
    const int cCol = blockIdx.x;   // 0..3
    const int cRow = blockIdx.y;   // 0..156

    const int tx = tid & 15;       // 0..15
    const int ty = tid >> 4;       // 0..15

    const int aRow = tid >> 1;           // 0..127
    const int aCol = (tid & 1) * 4;      // 0 or 4
    const int bRow = tid >> 5;           // 0..7
    const int bCol = (tid & 31) * 4;     // 0..124

    const int gARow = cRow * 128 + aRow;
    const bool aValid = (gARow < NN);
    const float* Ap = A + (size_t)gARow * K;
    const float* Bp = B + cCol * 128;

    float acc[8][8];
    #pragma unroll
    for (int i = 0; i < 8; i++)
        #pragma unroll
        for (int j = 0; j < 8; j++) acc[i][j] = 0.f;

    for (int k0 = 0; k0 < K; k0 += 8) {
        float4 av = aValid ? *(const float4*)(Ap + k0 + aCol)
                           : make_float4(0.f, 0.f, 0.f, 0.f);
        float4 bv = *(const float4*)(Bp + (size_t)(k0 + bRow) * N + bCol);
        As[aCol + 0][aRow] = av.x;
        As[aCol + 1][aRow] = av.y;
        As[aCol + 2][aRow] = av.z;
        As[aCol + 3][aRow] = av.w;
        *(float4*)&Bs[bRow][bCol] = bv;
        __syncthreads();

        #pragma unroll
        for (int k = 0; k < 8; k++) {
            float4 a0 = *(const float4*)&As[k][ty * 8];
            float4 a1 = *(const float4*)&As[k][ty * 8 + 4];
            float4 b0 = *(const float4*)&Bs[k][tx * 8];
            float4 b1 = *(const float4*)&Bs[k][tx * 8 + 4];
            float ra[8] = {a0.x, a0.y, a0.z, a0.w, a1.x, a1.y, a1.z, a1.w};
            float rb[8] = {b0.x, b0.y, b0.z, b0.w, b1.x, b1.y, b1.z, b1.w};
            #pragma unroll
            for (int i = 0; i < 8; i++)
                #pragma unroll
                for (int j = 0; j < 8; j++) acc[i][j] += ra[i] * rb[j];
        }
        __syncthreads();
    }

    #pragma unroll
    for (int i = 0; i < 8; i++) {
        int r = cRow * 128 + ty * 8 + i;
        if (r < NN) {
            float* cp = g_xl + (size_t)r * N + cCol * 128 + tx * 8;
            *(float4*)cp       = make_float4(acc[i][0], acc[i][1], acc[i][2], acc[i][3]);
            *(float4*)(cp + 4) = make_float4(acc[i][4], acc[i][5], acc[i][6], acc[i][7]);
        }
    }
}

// ---------------- per-node attention halves: warp per (node, head) ------
__global__ void k_attn_halves(const float* __restrict__ att_src,
                              const float* __restrict__ att_dst) {
    int warp = (blockIdx.x * blockDim.x + threadIdx.x) >> 5;
    int lane = threadIdx.x & 31;
    if (warp >= NN * NH) return;
    int n = warp >> 2, h = warp & 3;
    const float4* row = (const float4*)(g_xl + (size_t)n * HC + h * OC);
    const float4* s4  = (const float4*)(att_src + h * OC);
    const float4* d4  = (const float4*)(att_dst + h * OC);
    float4 v = row[lane], s = s4[lane], d = d4[lane];
    float ss = v.x * s.x + v.y * s.y + v.z * s.z + v.w * s.w;
    float dd = v.x * d.x + v.y * d.y + v.z * d.z + v.w * d.w;
    #pragma unroll
    for (int o = 16; o; o >>= 1) {
        ss += __shfl_down_sync(0xFFFFFFFFu, ss, o);
        dd += __shfl_down_sync(0xFFFFFFFFu, dd, o);
    }
    if (lane == 0) { g_as[warp] = ss; g_ad[warp] = dd; }
}

__device__ __forceinline__ void atomicMaxFloat(float* addr, float value) {
    if (value >= 0.f) atomicMax((int*)addr, __float_as_int(value));
    else              atomicMin((unsigned int*)addr, __float_as_uint(value));
}

__device__ __forceinline__ float leaky(float a) { return a > 0.f ? a : 0.2f * a; }

// ---------------- segment max over incoming edges (incl. self loops) ----
// edge_index is int32 on device (JAX x64 disabled downcasts int64 -> int32)
__global__ void k_edge_max(const int* __restrict__ ei) {
    int i = blockIdx.x * blockDim.x + threadIdx.x;
    const int tot = (NE + NN) * NH;
    if (i >= tot) return;
    int e = i >> 2, h = i & 3;
    int src, dst;
    if (e < NE) { src = ei[e]; dst = ei[NE + e]; }
    else        { src = dst = e - NE; }
    float a = leaky(g_as[src * NH + h] + g_ad[dst * NH + h]);
    atomicMaxFloat(&g_amax[dst * NH + h], a);
}

// ---------------- segment sum of exp(alpha - max) -----------------------
__global__ void k_edge_sum(const int* __restrict__ ei) {
    int i = blockIdx.x * blockDim.x + threadIdx.x;
    const int tot = (NE + NN) * NH;
    if (i >= tot) return;
    int e = i >> 2, h = i & 3;
    int src, dst;
    if (e < NE) { src = ei[e]; dst = ei[NE + e]; }
    else        { src = dst = e - NE; }
    float a = leaky(g_as[src * NH + h] + g_ad[dst * NH + h]);
    float ae = expf(a - g_amax[dst * NH + h]);
    atomicAdd(&g_den[dst * NH + h], ae);
}

// ---------------- weighted scatter: warp per edge -----------------------
// out[dst, c] += sum_h w_eh * xl[src, h*128 + c]   (head-mean folded later)
__global__ __launch_bounds__(256) void k_scatter(const int* __restrict__ ei,
                                                 float* __restrict__ out) {
    int e    = (blockIdx.x * blockDim.x + threadIdx.x) >> 5;
    int lane = threadIdx.x & 31;
    const int tot = NE + NN;
    if (e >= tot) return;
    int src, dst;
    if (e < NE) { src = __ldg(&ei[e]); dst = __ldg(&ei[NE + e]); }
    else        { src = dst = e - NE; }

    float w = 0.f;
    if (lane < 4) {
        float a  = leaky(g_as[src * NH + lane] + g_ad[dst * NH + lane]);
        float ae = expf(a - g_amax[dst * NH + lane]);
        w = ae / (g_den[dst * NH + lane] + 1e-16f);
    }
    float w0 = __shfl_sync(0xFFFFFFFFu, w, 0);
    float w1 = __shfl_sync(0xFFFFFFFFu, w, 1);
    float w2 = __shfl_sync(0xFFFFFFFFu, w, 2);
    float w3 = __shfl_sync(0xFFFFFFFFu, w, 3);

    const float4* xr = (const float4*)(g_xl + (size_t)src * HC);
    float4 x0 = __ldg(&xr[lane]);
    float4 x1 = __ldg(&xr[32 + lane]);
    float4 x2 = __ldg(&xr[64 + lane]);
    float4 x3 = __ldg(&xr[96 + lane]);

    float4 r;
    r.x = w0 * x0.x + w1 * x1.x + w2 * x2.x + w3 * x3.x;
    r.y = w0 * x0.y + w1 * x1.y + w2 * x2.y + w3 * x3.y;
    r.z = w0 * x0.z + w1 * x1.z + w2 * x2.z + w3 * x3.z;
    r.w = w0 * x0.w + w1 * x1.w + w2 * x2.w + w3 * x3.w;

    float* dp = out + (size_t)dst * OC + lane * 4;
    asm volatile("red.global.add.v4.f32 [%0], {%1, %2, %3, %4};"
                 :: "l"(dp), "f"(r.x), "f"(r.y), "f"(r.z), "f"(r.w)
                 : "memory");
}

// ---------------- finalize: elu(mean_h + bias), in place ----------------
__global__ void k_final(float* __restrict__ out, const float* __restrict__ bias) {
    int i = blockIdx.x * blockDim.x + threadIdx.x;
    if (i >= NN * OC) return;
    float v = out[i] * 0.25f + bias[i & (OC - 1)];
    out[i] = v > 0.f ? v : expm1f(v);
}

// ========================================================================
extern "C" void kernel_launch(void* const* d_in, const int* in_sizes, int n_in,
                              void* d_out, int out_size) {
    const float* x       = (const float*)d_in[0];
    const float* W       = (const float*)d_in[1];
    const float* att_src = (const float*)d_in[2];
    const float* att_dst = (const float*)d_in[3];
    const float* bias    = (const float*)d_in[4];
    const int*   ei      = (const int*)d_in[5];
    float* out = (float*)d_out;

    // init accumulator + segment state
    k_init<<<(NN * OC + 255) / 256, 256>>>(out);

    // xl = x @ W
    dim3 ggrid(4, (NN + 127) / 128);
    k_gemm<<<ggrid, 256>>>(x, W);

    // per-node attention halves (warp per (node, head))
    k_attn_halves<<<(NN * NH * 32 + 255) / 256, 256>>>(att_src, att_dst);

    // segment softmax over edges + self-loops
    const int etot4 = (NE + NN) * NH;
    k_edge_max<<<(etot4 + 255) / 256, 256>>>(ei);
    k_edge_sum<<<(etot4 + 255) / 256, 256>>>(ei);

    // weighted scatter (warp per edge)
    const int etot = NE + NN;
    k_scatter<<<(etot * 32 + 255) / 256, 256>>>(ei, out);

    // mean over heads + bias + elu
    k_final<<<(NN * OC + 255) / 256, 256>>>(out, bias);
}

// round 4
// speedup vs baseline: 1.4745x; 1.4745x over previous
#include <cuda_runtime.h>
#include <cfloat>
#include <math.h>
#include <cstdint>
#include <mma.h>

using namespace nvcuda;

// Problem constants
#define NN   20000
#define NE   320000
#define HC   512
#define NH   4
#define OC   128
#define KDIM 512
#define NDIM 512

// -------- scratch (g_xl padded: last M-block stores rows up to 20095) ----
__device__ float g_xl[(size_t)(NN + 128) * HC];
__device__ float g_as[NN * NH];
__device__ float g_ad[NN * NH];
__device__ float g_amax[NN * NH];
__device__ float g_den[NN * NH];

// ---------------- init ----------------
__global__ void k_init(float* __restrict__ out) {
    int i = blockIdx.x * blockDim.x + threadIdx.x;
    if (i < NN * OC) out[i] = 0.f;
    if (i < NN * NH) { g_amax[i] = -FLT_MAX; g_den[i] = 0.f; }
}

// ---------------- GEMM: g_xl = x @ W (tf32 wmma, 128x128x32 tiles) -------
#define BLK_K  32
#define LDA_S  36      // 128 x 36 floats (padded)
#define LDB_S  136     // 32 x 136 floats (padded)
#define A_FLOATS (128 * LDA_S)
#define B_FLOATS (BLK_K * LDB_S)
#define STAGE_FLOATS (A_FLOATS + B_FLOATS)
#define GEMM_SMEM (2 * STAGE_FLOATS * 4)

__device__ __forceinline__ uint32_t smem_u32(const void* p) {
    uint32_t a;
    asm("{ .reg .u64 t; cvta.to.shared.u64 t, %1; cvt.u32.u64 %0, t; }" : "=r"(a) : "l"(p));
    return a;
}

__global__ __launch_bounds__(256) void k_gemm_tc(const float* __restrict__ x,
                                                 const float* __restrict__ W) {
    extern __shared__ float smem[];
    float* As = smem;                     // [2][128][LDA_S]
    float* Bs = smem + 2 * A_FLOATS;      // [2][BLK_K][LDB_S]

    const int tid = threadIdx.x;
    const int warpId = tid >> 5;
    const int warpM = warpId & 3;         // 0..3 -> 32-row slab
    const int warpN = warpId >> 2;        // 0..1 -> 64-col slab
    const int m0 = blockIdx.y * 128;
    const int n0 = blockIdx.x * 128;

    const uint32_t sA = smem_u32(As);
    const uint32_t sB = smem_u32(Bs);

    // async stage loader: A rows m0..m0+127 (k window), B rows k..k+31 (n window)
    auto load_stage = [&](int kc, int buf) {
        const int k0 = kc * BLK_K;
        #pragma unroll
        for (int it = 0; it < 4; it++) {
            int id = tid + it * 256;
            int r = id >> 3, q = id & 7;         // r: 0..127, q: 0..7 (16B seg)
            int grow = m0 + r;
            const float* gp = x + (size_t)(grow < NN ? grow : 0) * KDIM + k0 + q * 4;
            int sz = (grow < NN) ? 16 : 0;
            uint32_t so = sA + (buf * A_FLOATS + r * LDA_S + q * 4) * 4;
            asm volatile("cp.async.cg.shared.global [%0], [%1], 16, %2;"
                         :: "r"(so), "l"(gp), "r"(sz));
        }
        #pragma unroll
        for (int it = 0; it < 4; it++) {
            int id = tid + it * 256;
            int r = id >> 5, q = id & 31;        // r: 0..31, q: 0..31
            const float* gp = W + (size_t)(k0 + r) * NDIM + n0 + q * 4;
            uint32_t so = sB + (buf * B_FLOATS + r * LDB_S + q * 4) * 4;
            asm volatile("cp.async.cg.shared.global [%0], [%1], 16;"
                         :: "r"(so), "l"(gp));
        }
        asm volatile("cp.async.commit_group;" ::: "memory");
    };

    wmma::fragment<wmma::accumulator, 16, 16, 8, float> acc[2][4];
    #pragma unroll
    for (int i = 0; i < 2; i++)
        #pragma unroll
        for (int j = 0; j < 4; j++) wmma::fill_fragment(acc[i][j], 0.f);

    load_stage(0, 0);

    const int NCHUNK = KDIM / BLK_K;   // 16
    for (int kc = 0; kc < NCHUNK; kc++) {
        const int buf = kc & 1;
        if (kc + 1 < NCHUNK) load_stage(kc + 1, buf ^ 1);
        // wait for current stage (1 group in flight = the prefetch)
        if (kc + 1 < NCHUNK)
            asm volatile("cp.async.wait_group 1;" ::: "memory");
        else
            asm volatile("cp.async.wait_group 0;" ::: "memory");
        __syncthreads();

        const float* Ab = As + buf * A_FLOATS + warpM * 32 * LDA_S;
        const float* Bb = Bs + buf * B_FLOATS + warpN * 64;
        #pragma unroll
        for (int ks = 0; ks < BLK_K / 8; ks++) {
            wmma::fragment<wmma::matrix_a, 16, 16, 8, wmma::precision::tf32, wmma::row_major> af[2];
            wmma::fragment<wmma::matrix_b, 16, 16, 8, wmma::precision::tf32, wmma::row_major> bf[4];
            #pragma unroll
            for (int mt = 0; mt < 2; mt++) {
                wmma::load_matrix_sync(af[mt], Ab + mt * 16 * LDA_S + ks * 8, LDA_S);
                #pragma unroll
                for (int e = 0; e < af[mt].num_elements; e++)
                    af[mt].x[e] = wmma::__float_to_tf32(af[mt].x[e]);
            }
            #pragma unroll
            for (int nt = 0; nt < 4; nt++) {
                wmma::load_matrix_sync(bf[nt], Bb + ks * 8 * LDB_S + nt * 16, LDB_S);
                #pragma unroll
                for (int e = 0; e < bf[nt].num_elements; e++)
                    bf[nt].x[e] = wmma::__float_to_tf32(bf[nt].x[e]);
            }
            #pragma unroll
            for (int mt = 0; mt < 2; mt++)
                #pragma unroll
                for (int nt = 0; nt < 4; nt++)
                    wmma::mma_sync(acc[mt][nt], af[mt], bf[nt], acc[mt][nt]);
        }
        __syncthreads();
    }

    // epilogue: g_xl is padded, store unguarded
    #pragma unroll
    for (int mt = 0; mt < 2; mt++) {
        int row = m0 + warpM * 32 + mt * 16;
        #pragma unroll
        for (int nt = 0; nt < 4; nt++) {
            int col = n0 + warpN * 64 + nt * 16;
            wmma::store_matrix_sync(g_xl + (size_t)row * NDIM + col, acc[mt][nt],
                                    NDIM, wmma::mem_row_major);
        }
    }
}

// ---------------- per-node attention halves ----------------
__global__ void k_attn_halves(const float* __restrict__ att_src,
                              const float* __restrict__ att_dst) {
    int warp = (blockIdx.x * blockDim.x + threadIdx.x) >> 5;
    int lane = threadIdx.x & 31;
    if (warp >= NN * NH) return;
    int n = warp >> 2, h = warp & 3;
    const float4* row = (const float4*)(g_xl + (size_t)n * HC + h * OC);
    const float4* s4  = (const float4*)(att_src + h * OC);
    const float4* d4  = (const float4*)(att_dst + h * OC);
    float4 v = row[lane], s = s4[lane], d = d4[lane];
    float ss = v.x * s.x + v.y * s.y + v.z * s.z + v.w * s.w;
    float dd = v.x * d.x + v.y * d.y + v.z * d.z + v.w * d.w;
    #pragma unroll
    for (int o = 16; o; o >>= 1) {
        ss += __shfl_down_sync(0xFFFFFFFFu, ss, o);
        dd += __shfl_down_sync(0xFFFFFFFFu, dd, o);
    }
    if (lane == 0) { g_as[warp] = ss; g_ad[warp] = dd; }
}

__device__ __forceinline__ void atomicMaxFloat(float* addr, float value) {
    if (value >= 0.f) atomicMax((int*)addr, __float_as_int(value));
    else              atomicMin((unsigned int*)addr, __float_as_uint(value));
}
__device__ __forceinline__ float leaky(float a) { return a > 0.f ? a : 0.2f * a; }

// ---------------- segment max ----------------
__global__ void k_edge_max(const int* __restrict__ ei) {
    int i = blockIdx.x * blockDim.x + threadIdx.x;
    const int tot = (NE + NN) * NH;
    if (i >= tot) return;
    int e = i >> 2, h = i & 3;
    int src, dst;
    if (e < NE) { src = ei[e]; dst = ei[NE + e]; }
    else        { src = dst = e - NE; }
    float a = leaky(g_as[src * NH + h] + g_ad[dst * NH + h]);
    atomicMaxFloat(&g_amax[dst * NH + h], a);
}

// ---------------- segment sum ----------------
__global__ void k_edge_sum(const int* __restrict__ ei) {
    int i = blockIdx.x * blockDim.x + threadIdx.x;
    const int tot = (NE + NN) * NH;
    if (i >= tot) return;
    int e = i >> 2, h = i & 3;
    int src, dst;
    if (e < NE) { src = ei[e]; dst = ei[NE + e]; }
    else        { src = dst = e - NE; }
    float a = leaky(g_as[src * NH + h] + g_ad[dst * NH + h]);
    float ae = expf(a - g_amax[dst * NH + h]);
    atomicAdd(&g_den[dst * NH + h], ae);
}

// ---------------- weighted scatter: warp per edge ----------------
__global__ __launch_bounds__(256) void k_scatter(const int* __restrict__ ei,
                                                 float* __restrict__ out) {
    int e    = (blockIdx.x * blockDim.x + threadIdx.x) >> 5;
    int lane = threadIdx.x & 31;
    const int tot = NE + NN;
    if (e >= tot) return;
    int src, dst;
    if (e < NE) { src = __ldg(&ei[e]); dst = __ldg(&ei[NE + e]); }
    else        { src = dst = e - NE; }

    float w = 0.f;
    if (lane < 4) {
        float a  = leaky(g_as[src * NH + lane] + g_ad[dst * NH + lane]);
        float ae = expf(a - g_amax[dst * NH + lane]);
        w = ae / (g_den[dst * NH + lane] + 1e-16f);
    }
    float w0 = __shfl_sync(0xFFFFFFFFu, w, 0);
    float w1 = __shfl_sync(0xFFFFFFFFu, w, 1);
    float w2 = __shfl_sync(0xFFFFFFFFu, w, 2);
    float w3 = __shfl_sync(0xFFFFFFFFu, w, 3);

    const float4* xr = (const float4*)(g_xl + (size_t)src * HC);
    float4 x0 = __ldg(&xr[lane]);
    float4 x1 = __ldg(&xr[32 + lane]);
    float4 x2 = __ldg(&xr[64 + lane]);
    float4 x3 = __ldg(&xr[96 + lane]);

    float4 r;
    r.x = w0 * x0.x + w1 * x1.x + w2 * x2.x + w3 * x3.x;
    r.y = w0 * x0.y + w1 * x1.y + w2 * x2.y + w3 * x3.y;
    r.z = w0 * x0.z + w1 * x1.z + w2 * x2.z + w3 * x3.z;
    r.w = w0 * x0.w + w1 * x1.w + w2 * x2.w + w3 * x3.w;

    float* dp = out + (size_t)dst * OC + lane * 4;
    asm volatile("red.global.add.v4.f32 [%0], {%1, %2, %3, %4};"
                 :: "l"(dp), "f"(r.x), "f"(r.y), "f"(r.z), "f"(r.w)
                 : "memory");
}

// ---------------- finalize ----------------
__global__ void k_final(float* __restrict__ out, const float* __restrict__ bias) {
    int i = blockIdx.x * blockDim.x + threadIdx.x;
    if (i >= NN * OC) return;
    float v = out[i] * 0.25f + bias[i & (OC - 1)];
    out[i] = v > 0.f ? v : expm1f(v);
}

// ========================================================================
extern "C" void kernel_launch(void* const* d_in, const int* in_sizes, int n_in,
                              void* d_out, int out_size) {
    const float* x       = (const float*)d_in[0];
    const float* W       = (const float*)d_in[1];
    const float* att_src = (const float*)d_in[2];
    const float* att_dst = (const float*)d_in[3];
    const float* bias    = (const float*)d_in[4];
    const int*   ei      = (const int*)d_in[5];
    float* out = (float*)d_out;

    static bool attr_set = false;
    if (!attr_set) {
        cudaFuncSetAttribute(k_gemm_tc, cudaFuncAttributeMaxDynamicSharedMemorySize,
                             GEMM_SMEM);
        attr_set = true;
    }

    k_init<<<(NN * OC + 255) / 256, 256>>>(out);

    dim3 ggrid(NDIM / 128, (NN + 127) / 128);   // (4, 157)
    k_gemm_tc<<<ggrid, 256, GEMM_SMEM>>>(x, W);

    k_attn_halves<<<(NN * NH * 32 + 255) / 256, 256>>>(att_src, att_dst);

    const int etot4 = (NE + NN) * NH;
    k_edge_max<<<(etot4 + 255) / 256, 256>>>(ei);
    k_edge_sum<<<(etot4 + 255) / 256, 256>>>(ei);

    const int etot = NE + NN;
    k_scatter<<<(etot * 32 + 255) / 256, 256>>>(ei, out);

    k_final<<<(NN * OC + 255) / 256, 256>>>(out, bias);
}